// round 5
// baseline (speedup 1.0000x reference)
#include <cuda_runtime.h>
#include <cuda_bf16.h>
#include <cstdint>

// Problem constants (LengthRegulator_42691974922415):
//   pred_duration:           [B=32, L=512] int32, values in [0, 8)
//   phoneme_hidden_sequence: [B=32, L=512, D=384] float32
//   output:                  [B=32, T=L*7=3584, D=384] float32
static constexpr int B  = 32;
static constexpr int L  = 512;
static constexpr int D  = 384;
static constexpr int T  = 3584;       // L * (DUR_MAX-1)
static constexpr int D4 = D / 4;      // 96 float4 per row

// Scratch: frame -> source hidden-row id (b*L + l), or -1 for zero frames.
// 32*3584 ints = 458 KB static device memory (no runtime allocation).
__device__ int g_frame_idx[B * T];

// ---------------------------------------------------------------------------
// Kernel 1: per-batch duration scan + frame-index scatter.
// One block per batch, 512 threads (one per phoneme).
// ---------------------------------------------------------------------------
__global__ void __launch_bounds__(L) build_index_kernel(const int* __restrict__ dur)
{
    const int b   = blockIdx.x;
    const int tid = threadIdx.x;           // phoneme index l
    const int lane = tid & 31;
    const int w    = tid >> 5;             // warp id, 0..15

    int d = dur[b * L + tid];

    // Warp-level inclusive scan.
    int x = d;
    #pragma unroll
    for (int o = 1; o < 32; o <<= 1) {
        int y = __shfl_up_sync(0xffffffffu, x, o);
        if (lane >= o) x += y;
    }

    __shared__ int wsum[16];
    if (lane == 31) wsum[w] = x;
    __syncthreads();

    // Scan the 16 warp totals (warp 0, full-mask shuffles).
    if (w == 0) {
        int s = (lane < 16) ? wsum[lane] : 0;
        #pragma unroll
        for (int o = 1; o < 16; o <<= 1) {
            int y = __shfl_up_sync(0xffffffffu, s, o);
            if (lane >= o) s += y;
        }
        if (lane < 16) wsum[lane] = s;
    }
    __syncthreads();

    const int incl  = x + (w > 0 ? wsum[w - 1] : 0);  // inclusive cumsum
    const int start = incl - d;                       // exclusive start frame

    // Fill this batch's frame map with -1 (zero frames), then scatter.
    int* fi = g_frame_idx + b * T;
    #pragma unroll
    for (int t = tid; t < T; t += L) fi[t] = -1;
    __syncthreads();

    const int src = b * L + tid;
    for (int k = 0; k < d; ++k)           // d <= 7
        fi[start + k] = src;
}

// ---------------------------------------------------------------------------
// Kernel 2: streaming expand with ILP=8.
//   total float4 = B*T*D4 = 11,010,048 = 5376 blocks * 256 threads * 8
// Each thread handles 8 float4s at (base + tid + k*256): every store slice is
// a fully-coalesced 256-thread span; 8 independent idx-loads / hid-loads /
// stores per thread give MLP>=8 to hide the dependent-gather latency.
// Stores use .cs (evict-first) so the 176 MB output stream does not evict
// the 25 MB L2-resident hidden tensor.
// ---------------------------------------------------------------------------
static constexpr int ILP = 8;

__global__ void __launch_bounds__(256) expand_kernel(const float4* __restrict__ hid,
                                                     float4* __restrict__ out)
{
    const unsigned base = blockIdx.x * (256u * ILP) + threadIdx.x;

    int idx[ILP];
    int col[ILP];

    #pragma unroll
    for (int k = 0; k < ILP; ++k) {
        const unsigned i   = base + k * 256u;
        const unsigned row = i / D4;            // frame row (b*T + t)
        col[k]             = i - row * D4;      // float4 column within row
        idx[k]             = __ldg(&g_frame_idx[row]);   // 8 independent loads
    }

    float4 v[ILP];
    #pragma unroll
    for (int k = 0; k < ILP; ++k) {
        v[k] = make_float4(0.f, 0.f, 0.f, 0.f);
        if (idx[k] >= 0)
            v[k] = __ldg(&hid[idx[k] * D4 + col[k]]);    // 8 independent gathers
    }

    #pragma unroll
    for (int k = 0; k < ILP; ++k)
        __stcs(&out[base + k * 256u], v[k]);             // 8 independent streams
}

// ---------------------------------------------------------------------------
extern "C" void kernel_launch(void* const* d_in, const int* in_sizes, int n_in,
                              void* d_out, int out_size)
{
    const int*    dur = (const int*)d_in[0];            // [B, L] int32
    const float4* hid = (const float4*)d_in[1];         // [B, L, D] f32 as float4
    float4*       out = (float4*)d_out;                 // [B, T, D] f32 as float4

    build_index_kernel<<<B, L>>>(dur);

    const int n4 = B * T * D4;            // 11,010,048
    expand_kernel<<<n4 / (256 * ILP), 256>>>(hid, out);
}

// round 6
// speedup vs baseline: 1.0245x; 1.0245x over previous
#include <cuda_runtime.h>
#include <cuda_bf16.h>
#include <cstdint>

// Problem constants (LengthRegulator_42691974922415):
//   pred_duration:           [B=32, L=512] int32, values in [0, 8)
//   phoneme_hidden_sequence: [B=32, L=512, D=384] float32
//   output:                  [B=32, T=L*7=3584, D=384] float32
static constexpr int B  = 32;
static constexpr int L  = 512;
static constexpr int D  = 384;
static constexpr int T  = 3584;       // L * (DUR_MAX-1)
static constexpr int D4 = D / 4;      // 96 float4 per row

// Scratch: frame -> source hidden-row id (b*L + l), or -1 for zero frames.
// 32*3584 ints = 458 KB static device memory (no runtime allocation).
__device__ int g_frame_idx[B * T];

// ---------------------------------------------------------------------------
// Kernel 1: per-batch duration scan + frame-index scatter.
// One block per batch, 512 threads (one per phoneme).
// ---------------------------------------------------------------------------
__global__ void __launch_bounds__(L) build_index_kernel(const int* __restrict__ dur)
{
    const int b   = blockIdx.x;
    const int tid = threadIdx.x;           // phoneme index l
    const int lane = tid & 31;
    const int w    = tid >> 5;             // warp id, 0..15

    int d = dur[b * L + tid];

    // Warp-level inclusive scan.
    int x = d;
    #pragma unroll
    for (int o = 1; o < 32; o <<= 1) {
        int y = __shfl_up_sync(0xffffffffu, x, o);
        if (lane >= o) x += y;
    }

    __shared__ int wsum[16];
    if (lane == 31) wsum[w] = x;
    __syncthreads();

    // Scan the 16 warp totals (warp 0, full-mask shuffles).
    if (w == 0) {
        int s = (lane < 16) ? wsum[lane] : 0;
        #pragma unroll
        for (int o = 1; o < 16; o <<= 1) {
            int y = __shfl_up_sync(0xffffffffu, s, o);
            if (lane >= o) s += y;
        }
        if (lane < 16) wsum[lane] = s;
    }
    __syncthreads();

    const int incl  = x + (w > 0 ? wsum[w - 1] : 0);  // inclusive cumsum
    const int start = incl - d;                       // exclusive start frame

    // Fill this batch's frame map with -1 (zero frames), then scatter.
    int* fi = g_frame_idx + b * T;
    #pragma unroll
    for (int t = tid; t < T; t += L) fi[t] = -1;
    __syncthreads();

    const int src = b * L + tid;
    for (int k = 0; k < d; ++k)           // d <= 7
        fi[start + k] = src;
}

// ---------------------------------------------------------------------------
// Kernel 2: streaming expand with ILP=8 and an unlocked register budget.
//   total float4 = B*T*D4 = 11,010,048 = 5376 blocks * 256 threads * 8
// __launch_bounds__(256, 2) allows ~128 regs/thread so all 8 idx-loads /
// gathers / stores are genuinely in flight (round-5 showed that at a
// 32-reg budget ptxas serializes this body down to ~MLP 2-3).
// Stores use .cs (evict-first) so the 176 MB output stream does not evict
// the 25 MB L2-resident hidden tensor.
// ---------------------------------------------------------------------------
static constexpr int ILP = 8;

__global__ void __launch_bounds__(256, 2) expand_kernel(const float4* __restrict__ hid,
                                                        float4* __restrict__ out)
{
    const unsigned base = blockIdx.x * (256u * ILP) + threadIdx.x;

    int idx[ILP];
    int col[ILP];

    #pragma unroll
    for (int k = 0; k < ILP; ++k) {
        const unsigned i   = base + k * 256u;
        const unsigned row = i / D4;            // frame row (b*T + t)
        col[k]             = i - row * D4;      // float4 column within row
        idx[k]             = __ldg(&g_frame_idx[row]);   // 8 independent loads
    }

    float4 v[ILP];
    #pragma unroll
    for (int k = 0; k < ILP; ++k) {
        v[k] = make_float4(0.f, 0.f, 0.f, 0.f);
        if (idx[k] >= 0)
            v[k] = __ldg(&hid[idx[k] * D4 + col[k]]);    // 8 independent gathers
    }

    #pragma unroll
    for (int k = 0; k < ILP; ++k)
        __stcs(&out[base + k * 256u], v[k]);             // 8 independent streams
}

// ---------------------------------------------------------------------------
extern "C" void kernel_launch(void* const* d_in, const int* in_sizes, int n_in,
                              void* d_out, int out_size)
{
    const int*    dur = (const int*)d_in[0];            // [B, L] int32
    const float4* hid = (const float4*)d_in[1];         // [B, L, D] f32 as float4
    float4*       out = (float4*)d_out;                 // [B, T, D] f32 as float4

    build_index_kernel<<<B, L>>>(dur);

    const int n4 = B * T * D4;            // 11,010,048
    expand_kernel<<<n4 / (256 * ILP), 256>>>(hid, out);
}